// round 5
// baseline (speedup 1.0000x reference)
#include <cuda_runtime.h>

#define D 96
#define NMAX 50000
#define EMAX 800000
#define SCAN_B 512
#define NSCANBLK ((NMAX + SCAN_B - 1) / SCAN_B)   // 98

typedef unsigned long long ull;

// ---------------- scratch (static device globals; no allocation) ----------
__device__ int   g_counts[NMAX];
__device__ int   g_rowptr[NMAX + 1];
__device__ int   g_cursor[NMAX];
__device__ float g_dinv[NMAX];
__device__ int2  g_adj[EMAX];                 // {src, bitcast(norm)}
__device__ float g_h1[(size_t)NMAX * D];      // ping buffer
__device__ float g_h2[(size_t)NMAX * D];      // pong buffer
__device__ int   g_blockSums[NSCANBLK + 2];

// ---------------- packed f32x2 helpers -------------------------------------
__device__ __forceinline__ ull pack2(float lo, float hi) {
    ull r; asm("mov.b64 %0, {%1, %2};" : "=l"(r) : "f"(lo), "f"(hi)); return r;
}
__device__ __forceinline__ void unpack2(ull v, float& lo, float& hi) {
    asm("mov.b64 {%0, %1}, %2;" : "=f"(lo), "=f"(hi) : "l"(v));
}
__device__ __forceinline__ void ffma2(ull& d, ull a, ull b) {
    asm("fma.rn.f32x2 %0, %1, %2, %0;" : "+l"(d) : "l"(a), "l"(b));
}

// ---------------- graph preprocessing -------------------------------------
__global__ void k_zero_counts(int n) {
    int i = blockIdx.x * blockDim.x + threadIdx.x;
    if (i < n) g_counts[i] = 0;
}

// edge_index is int32 (JAX x64 disabled downcasts int64 -> int32)
__global__ void k_hist(const int* __restrict__ ei, int E) {
    int e = blockIdx.x * blockDim.x + threadIdx.x;
    if (e < E) {
        int d = ei[E + e];
        atomicAdd(&g_counts[d], 1);
    }
}

// block-local exclusive scan of counts -> g_rowptr, block totals -> g_blockSums
// also computes dinv (fused; counts are already final here).
__global__ void k_scan1(int n) {
    __shared__ int wsum[16];
    int i = blockIdx.x * SCAN_B + threadIdx.x;
    int lane = threadIdx.x & 31, wid = threadIdx.x >> 5;
    int v = (i < n) ? g_counts[i] : 0;
    if (i < n) g_dinv[i] = rsqrtf((float)(v + 1));   // +1 self loop
    int x = v;
#pragma unroll
    for (int o = 1; o < 32; o <<= 1) {
        int t = __shfl_up_sync(0xFFFFFFFFu, x, o);
        if (lane >= o) x += t;
    }
    if (lane == 31) wsum[wid] = x;
    __syncthreads();
    if (wid == 0) {
        int s = (lane < 16) ? wsum[lane] : 0;
#pragma unroll
        for (int o = 1; o < 16; o <<= 1) {
            int t = __shfl_up_sync(0xFFFFFFFFu, s, o);
            if (lane >= o) s += t;
        }
        if (lane < 16) wsum[lane] = s;
    }
    __syncthreads();
    int base = (wid > 0) ? wsum[wid - 1] : 0;
    if (i < n) g_rowptr[i] = base + x - v;           // exclusive
    if (threadIdx.x == SCAN_B - 1) g_blockSums[blockIdx.x] = base + x;
}

// parallel scan of the (<=128) block sums
__global__ void k_scan2(int nb, int n) {
    __shared__ int s[128];
    int t = threadIdx.x;
    int v = (t < nb) ? g_blockSums[t] : 0;
    s[t] = v;
    __syncthreads();
    for (int off = 1; off < 128; off <<= 1) {
        int u = (t >= off) ? s[t - off] : 0;
        __syncthreads();
        s[t] += u;
        __syncthreads();
    }
    if (t < nb) g_blockSums[t] = s[t] - v;   // exclusive
    if (t == 127) g_rowptr[n] = s[127];      // total = E
}

__global__ void k_scan3(int n) {
    int i = blockIdx.x * SCAN_B + threadIdx.x;
    if (i < n) {
        int v = g_rowptr[i] + g_blockSums[blockIdx.x];
        g_rowptr[i] = v;
        g_cursor[i] = v;
    }
}

__global__ void k_scatter(const int* __restrict__ ei, int E) {
    int e = blockIdx.x * blockDim.x + threadIdx.x;
    if (e < E) {
        int s = ei[e];
        int d = ei[E + e];
        int pos = atomicAdd(&g_cursor[d], 1);
        float norm = g_dinv[s] * g_dinv[d];
        g_adj[pos] = make_int2(s, __float_as_int(norm));
    }
}

// ---------------- dense GEMM: Y[N,96] = X[N,96] @ W[96,96] -----------------
// Packed f32x2: two adjacent node rows share one 64-bit accumulator lane.
// block: (96,2) = 192 threads, TM=32 nodes. Thread (tx,ty): feature tx,
// node-pairs [ty*8, ty*8+8). src_sel: 0 = Xext, 1 = g_h2. Output g_h1.
#define TM 32
__global__ __launch_bounds__(192) void k_gemm(const float* __restrict__ Xext,
                                              const float* __restrict__ W,
                                              int n, int src_sel) {
    __shared__ __align__(16) float Ws[96 * 96];
    __shared__ __align__(16) ull Xs2[16][96];   // Xs2[p][k] = {X[2p][k], X[2p+1][k]}
    const float* X = src_sel ? (const float*)g_h2 : Xext;
    float* Y = (float*)g_h1;

    int tx = threadIdx.x;               // output feature (0..95)
    int ty = threadIdx.y;               // 0..1
    int tid = ty * 96 + tx;

    for (int i = tid; i < 96 * 96; i += 192) Ws[i] = W[i];

    int n0 = blockIdx.x * TM;
    int rows = min(TM, n - n0);
    float* Xsf = (float*)&Xs2[0][0];
    for (int i = tid; i < TM * 96; i += 192) {
        int m = i / 96, k = i % 96;     // coalesced global read
        float v = (m < rows) ? X[(size_t)(n0 + m) * 96 + k] : 0.f;
        Xsf[((m >> 1) * 96 + k) * 2 + (m & 1)] = v;
    }
    __syncthreads();

    ull acc[8];
#pragma unroll
    for (int j = 0; j < 8; j++) acc[j] = 0ull;

    int pbase = ty * 8;
#pragma unroll 4
    for (int k = 0; k < 96; k += 2) {
        float wa = Ws[k * 96 + tx];
        float wb = Ws[(k + 1) * 96 + tx];
        ull w0 = pack2(wa, wa);
        ull w1 = pack2(wb, wb);
#pragma unroll
        for (int j = 0; j < 8; j++) {
            ulonglong2 xv = *(const ulonglong2*)&Xs2[pbase + j][k];  // 16B, k even
            ffma2(acc[j], xv.x, w0);
            ffma2(acc[j], xv.y, w1);
        }
    }

#pragma unroll
    for (int j = 0; j < 8; j++) {
        float lo, hi;
        unpack2(acc[j], lo, hi);
        int m0 = (pbase + j) * 2;
        if (n0 + m0 < n)     Y[(size_t)(n0 + m0) * 96 + tx]     = lo;
        if (n0 + m0 + 1 < n) Y[(size_t)(n0 + m0 + 1) * 96 + tx] = hi;
    }
}

// ---------------- aggregation: one warp per node ---------------------------
// reads g_h1; writes g_h2 (dst_sel=0) or external out (dst_sel=1).
// out[n,f] = b[f] + sum_{incoming e} h[src_e,f]*norm_e + h[n,f]*dinv[n]^2
__global__ __launch_bounds__(256) void k_agg(const float* __restrict__ bias,
                                             const float* __restrict__ aptr,
                                             float* __restrict__ outExt,
                                             int n, int do_prelu, int dst_sel) {
    int warp = (blockIdx.x * blockDim.x + threadIdx.x) >> 5;
    int lane = threadIdx.x & 31;
    if (warp >= n) return;

    const float* h = (const float*)g_h1;
    float* out = (dst_sel == 0) ? (float*)g_h2 : outExt;

    int f0 = lane, f1 = lane + 32, f2 = lane + 64;
    float dn = g_dinv[warp];
    float dn2 = dn * dn;
    const float* hr = h + (size_t)warp * 96;
    float a0 = hr[f0] * dn2;
    float a1 = hr[f1] * dn2;
    float a2 = hr[f2] * dn2;

    int e = g_rowptr[warp];
    int end = g_rowptr[warp + 1];

    // 4-wide: 12 outstanding 128B gathers per warp per iteration
    for (; e + 3 < end; e += 4) {
        int2 q0 = g_adj[e],     q1 = g_adj[e + 1];
        int2 q2 = g_adj[e + 2], q3 = g_adj[e + 3];
        const float* r0 = h + (size_t)q0.x * 96;
        const float* r1 = h + (size_t)q1.x * 96;
        const float* r2 = h + (size_t)q2.x * 96;
        const float* r3 = h + (size_t)q3.x * 96;
        float n0 = __int_as_float(q0.y), n1 = __int_as_float(q1.y);
        float n2 = __int_as_float(q2.y), n3 = __int_as_float(q3.y);
        float v00 = r0[f0], v01 = r0[f1], v02 = r0[f2];
        float v10 = r1[f0], v11 = r1[f1], v12 = r1[f2];
        float v20 = r2[f0], v21 = r2[f1], v22 = r2[f2];
        float v30 = r3[f0], v31 = r3[f1], v32 = r3[f2];
        a0 = fmaf(v00, n0, a0); a1 = fmaf(v01, n0, a1); a2 = fmaf(v02, n0, a2);
        a0 = fmaf(v10, n1, a0); a1 = fmaf(v11, n1, a1); a2 = fmaf(v12, n1, a2);
        a0 = fmaf(v20, n2, a0); a1 = fmaf(v21, n2, a1); a2 = fmaf(v22, n2, a2);
        a0 = fmaf(v30, n3, a0); a1 = fmaf(v31, n3, a1); a2 = fmaf(v32, n3, a2);
    }
    for (; e < end; e++) {
        int2 q = g_adj[e];
        const float* r = h + (size_t)q.x * 96;
        float nn = __int_as_float(q.y);
        a0 = fmaf(r[f0], nn, a0);
        a1 = fmaf(r[f1], nn, a1);
        a2 = fmaf(r[f2], nn, a2);
    }

    a0 += bias[f0]; a1 += bias[f1]; a2 += bias[f2];
    if (do_prelu) {
        float a = aptr[0];
        a0 = (a0 > 0.f) ? a0 : a * a0;
        a1 = (a1 > 0.f) ? a1 : a * a1;
        a2 = (a2 > 0.f) ? a2 : a * a2;
    }
    float* o = out + (size_t)warp * 96;
    o[f0] = a0; o[f1] = a1; o[f2] = a2;
}

// ---------------- launch ---------------------------------------------------
extern "C" void kernel_launch(void* const* d_in, const int* in_sizes, int n_in,
                              void* d_out, int out_size) {
    const float* x  = (const float*)d_in[0];
    const int*   ei = (const int*)d_in[1];      // int32! (JAX x64 disabled)
    const float* W1 = (const float*)d_in[2];
    const float* b1 = (const float*)d_in[3];
    const float* a1 = (const float*)d_in[4];
    const float* W2 = (const float*)d_in[5];
    const float* b2 = (const float*)d_in[6];
    float*       out = (float*)d_out;

    int N = in_sizes[0] / D;
    int E = in_sizes[1] / 2;

    int nscan = (N + SCAN_B - 1) / SCAN_B;
    int gemm_blocks = (N + TM - 1) / TM;
    dim3 gemm_threads(96, 2);
    int agg_blocks = (N * 32 + 255) / 256;

    // GEMM1 is independent of the CSR build — run it first.
    k_gemm<<<gemm_blocks, gemm_threads>>>(x, W1, N, 0);

    // graph preprocessing (shared by both layers); dinv fused into scan1
    k_zero_counts<<<(N + 255) / 256, 256>>>(N);
    k_hist<<<(E + 255) / 256, 256>>>(ei, E);
    k_scan1<<<nscan, SCAN_B>>>(N);
    k_scan2<<<1, 128>>>(nscan, N);
    k_scan3<<<nscan, SCAN_B>>>(N);
    k_scatter<<<(E + 255) / 256, 256>>>(ei, E);

    // layer 1 aggregate + PReLU -> g_h2
    k_agg<<<agg_blocks, 256>>>(b1, a1, out, N, 1, 0);
    // layer 2: g_h2 @ W2 -> g_h1 ; aggregate -> out
    k_gemm<<<gemm_blocks, gemm_threads>>>(x /*unused*/, W2, N, 1);
    k_agg<<<agg_blocks, 256>>>(b2, a1, out, N, 0, 1);
}

// round 6
// speedup vs baseline: 1.1015x; 1.1015x over previous
#include <cuda_runtime.h>

#define D 96
#define NMAX 50000
#define EMAX 800000
#define SCAN_B 512
#define NSCANBLK ((NMAX + SCAN_B - 1) / SCAN_B)   // 98

typedef unsigned long long ull;

// ---------------- scratch (static device globals; no allocation) ----------
__device__ int   g_counts[NMAX];
__device__ int   g_rowptr[NMAX + 1];
__device__ int   g_cursor[NMAX];
__device__ float g_dinv[NMAX];
__device__ int2  g_adj[EMAX];                 // {src, bitcast(norm)}
__device__ float g_h1[(size_t)NMAX * D];      // ping buffer
__device__ float g_h2[(size_t)NMAX * D];      // pong buffer
__device__ int   g_blockSums[NSCANBLK + 2];

// ---------------- packed f32x2 helpers -------------------------------------
__device__ __forceinline__ ull pack2(float lo, float hi) {
    ull r; asm("mov.b64 %0, {%1, %2};" : "=l"(r) : "f"(lo), "f"(hi)); return r;
}
__device__ __forceinline__ void unpack2(ull v, float& lo, float& hi) {
    asm("mov.b64 {%0, %1}, %2;" : "=f"(lo), "=f"(hi) : "l"(v));
}
__device__ __forceinline__ void ffma2(ull& d, ull a, ull b) {
    asm("fma.rn.f32x2 %0, %1, %2, %0;" : "+l"(d) : "l"(a), "l"(b));
}

// ---------------- graph preprocessing -------------------------------------
__global__ void k_zero_counts(int n) {
    int i = blockIdx.x * blockDim.x + threadIdx.x;
    if (i < n) g_counts[i] = 0;
}

// edge_index is int32 (JAX x64 disabled downcasts int64 -> int32)
__global__ void k_hist(const int* __restrict__ ei, int E) {
    int e = blockIdx.x * blockDim.x + threadIdx.x;
    if (e < E) {
        int d = ei[E + e];
        atomicAdd(&g_counts[d], 1);
    }
}

// block-local exclusive scan of counts -> g_rowptr, block totals -> g_blockSums
// also computes dinv (fused; counts are final here).
__global__ void k_scan1(int n) {
    __shared__ int wsum[16];
    int i = blockIdx.x * SCAN_B + threadIdx.x;
    int lane = threadIdx.x & 31, wid = threadIdx.x >> 5;
    int v = (i < n) ? g_counts[i] : 0;
    if (i < n) g_dinv[i] = rsqrtf((float)(v + 1));   // +1 self loop
    int x = v;
#pragma unroll
    for (int o = 1; o < 32; o <<= 1) {
        int t = __shfl_up_sync(0xFFFFFFFFu, x, o);
        if (lane >= o) x += t;
    }
    if (lane == 31) wsum[wid] = x;
    __syncthreads();
    if (wid == 0) {
        int s = (lane < 16) ? wsum[lane] : 0;
#pragma unroll
        for (int o = 1; o < 16; o <<= 1) {
            int t = __shfl_up_sync(0xFFFFFFFFu, s, o);
            if (lane >= o) s += t;
        }
        if (lane < 16) wsum[lane] = s;
    }
    __syncthreads();
    int base = (wid > 0) ? wsum[wid - 1] : 0;
    if (i < n) g_rowptr[i] = base + x - v;           // exclusive
    if (threadIdx.x == SCAN_B - 1) g_blockSums[blockIdx.x] = base + x;
}

// parallel scan of the (<=128) block sums
__global__ void k_scan2(int nb, int n) {
    __shared__ int s[128];
    int t = threadIdx.x;
    int v = (t < nb) ? g_blockSums[t] : 0;
    s[t] = v;
    __syncthreads();
    for (int off = 1; off < 128; off <<= 1) {
        int u = (t >= off) ? s[t - off] : 0;
        __syncthreads();
        s[t] += u;
        __syncthreads();
    }
    if (t < nb) g_blockSums[t] = s[t] - v;   // exclusive
    if (t == 127) g_rowptr[n] = s[127];      // total = E
}

__global__ void k_scan3(int n) {
    int i = blockIdx.x * SCAN_B + threadIdx.x;
    if (i < n) {
        int v = g_rowptr[i] + g_blockSums[blockIdx.x];
        g_rowptr[i] = v;
        g_cursor[i] = v;
    }
}

__global__ void k_scatter(const int* __restrict__ ei, int E) {
    int e = blockIdx.x * blockDim.x + threadIdx.x;
    if (e < E) {
        int s = ei[e];
        int d = ei[E + e];
        int pos = atomicAdd(&g_cursor[d], 1);
        float norm = g_dinv[s] * g_dinv[d];
        g_adj[pos] = make_int2(s, __float_as_int(norm));
    }
}

// ---------------- dense GEMM: Y[N,96] = X[N,96] @ W[96,96] -----------------
// Register tile per thread: 4 contiguous features x 2 row-pairs (f32x2 packed).
// block: 192 threads, TM=32 nodes. tid -> f0=(tid%24)*4, p0=(tid/24)*2.
// smem: Ws 36KB + Xs2 12KB = 48KB. src_sel: 0 = Xext, 1 = g_h2. Out: g_h1.
#define TM 32
__global__ __launch_bounds__(192) void k_gemm(const float* __restrict__ Xext,
                                              const float* __restrict__ W,
                                              int n, int src_sel) {
    __shared__ __align__(16) float Ws[96 * 96];
    __shared__ __align__(16) ull Xs2[16][96];   // Xs2[p][k] = {X[2p][k], X[2p+1][k]}
    const float* X = src_sel ? (const float*)g_h2 : Xext;
    float* Y = (float*)g_h1;

    int tid = threadIdx.x;

    // stage W (vectorized, coalesced)
    {
        const float4* Wv = (const float4*)W;
        float4* Wsv = (float4*)Ws;
        for (int i = tid; i < 96 * 96 / 4; i += 192) Wsv[i] = Wv[i];
    }

    int n0 = blockIdx.x * TM;
    int rows = min(TM, n - n0);
    float* Xsf = (float*)&Xs2[0][0];
    for (int i = tid; i < TM * 96; i += 192) {
        int m = i / 96, k = i % 96;     // coalesced global read
        float v = (m < rows) ? X[(size_t)(n0 + m) * 96 + k] : 0.f;
        Xsf[((m >> 1) * 96 + k) * 2 + (m & 1)] = v;
    }
    __syncthreads();

    int f0 = (tid % 24) * 4;
    int p0 = (tid / 24) * 2;

    ull acc[4][2];
#pragma unroll
    for (int f = 0; f < 4; f++)
#pragma unroll
        for (int p = 0; p < 2; p++) acc[f][p] = 0ull;

#pragma unroll 6
    for (int k = 0; k < 96; k += 2) {
        float4 w0 = *(const float4*)&Ws[k * 96 + f0];
        float4 w1 = *(const float4*)&Ws[(k + 1) * 96 + f0];
        ulonglong2 x0 = *(const ulonglong2*)&Xs2[p0][k];
        ulonglong2 x1 = *(const ulonglong2*)&Xs2[p0 + 1][k];

        ull pw00 = pack2(w0.x, w0.x), pw01 = pack2(w0.y, w0.y);
        ull pw02 = pack2(w0.z, w0.z), pw03 = pack2(w0.w, w0.w);
        ull pw10 = pack2(w1.x, w1.x), pw11 = pack2(w1.y, w1.y);
        ull pw12 = pack2(w1.z, w1.z), pw13 = pack2(w1.w, w1.w);

        ffma2(acc[0][0], x0.x, pw00); ffma2(acc[1][0], x0.x, pw01);
        ffma2(acc[2][0], x0.x, pw02); ffma2(acc[3][0], x0.x, pw03);
        ffma2(acc[0][0], x0.y, pw10); ffma2(acc[1][0], x0.y, pw11);
        ffma2(acc[2][0], x0.y, pw12); ffma2(acc[3][0], x0.y, pw13);

        ffma2(acc[0][1], x1.x, pw00); ffma2(acc[1][1], x1.x, pw01);
        ffma2(acc[2][1], x1.x, pw02); ffma2(acc[3][1], x1.x, pw03);
        ffma2(acc[0][1], x1.y, pw10); ffma2(acc[1][1], x1.y, pw11);
        ffma2(acc[2][1], x1.y, pw12); ffma2(acc[3][1], x1.y, pw13);
    }

#pragma unroll
    for (int p = 0; p < 2; p++) {
        int m0 = (p0 + p) * 2;
        float4 lo4, hi4;
        unpack2(acc[0][p], lo4.x, hi4.x);
        unpack2(acc[1][p], lo4.y, hi4.y);
        unpack2(acc[2][p], lo4.z, hi4.z);
        unpack2(acc[3][p], lo4.w, hi4.w);
        if (n0 + m0 < n)     *(float4*)&Y[(size_t)(n0 + m0) * 96 + f0]     = lo4;
        if (n0 + m0 + 1 < n) *(float4*)&Y[(size_t)(n0 + m0 + 1) * 96 + f0] = hi4;
    }
}

// ---------------- aggregation: one warp per node ---------------------------
// reads g_h1; writes g_h2 (dst_sel=0) or external out (dst_sel=1).
// out[n,f] = b[f] + sum_{incoming e} h[src_e,f]*norm_e + h[n,f]*dinv[n]^2
__global__ __launch_bounds__(256) void k_agg(const float* __restrict__ bias,
                                             const float* __restrict__ aptr,
                                             float* __restrict__ outExt,
                                             int n, int do_prelu, int dst_sel) {
    int warp = (blockIdx.x * blockDim.x + threadIdx.x) >> 5;
    int lane = threadIdx.x & 31;
    if (warp >= n) return;

    const float* h = (const float*)g_h1;
    float* out = (dst_sel == 0) ? (float*)g_h2 : outExt;

    int f0 = lane, f1 = lane + 32, f2 = lane + 64;
    float dn = g_dinv[warp];
    float dn2 = dn * dn;
    const float* hr = h + (size_t)warp * 96;
    float a0 = hr[f0] * dn2;
    float a1 = hr[f1] * dn2;
    float a2 = hr[f2] * dn2;

    int e = g_rowptr[warp];
    int end = g_rowptr[warp + 1];

    for (; e + 1 < end; e += 2) {
        int2 q0 = g_adj[e];
        int2 q1 = g_adj[e + 1];
        const float* r0 = h + (size_t)q0.x * 96;
        const float* r1 = h + (size_t)q1.x * 96;
        float n0 = __int_as_float(q0.y);
        float n1 = __int_as_float(q1.y);
        float v00 = r0[f0], v01 = r0[f1], v02 = r0[f2];
        float v10 = r1[f0], v11 = r1[f1], v12 = r1[f2];
        a0 = fmaf(v00, n0, a0); a1 = fmaf(v01, n0, a1); a2 = fmaf(v02, n0, a2);
        a0 = fmaf(v10, n1, a0); a1 = fmaf(v11, n1, a1); a2 = fmaf(v12, n1, a2);
    }
    if (e < end) {
        int2 q = g_adj[e];
        const float* r = h + (size_t)q.x * 96;
        float nn = __int_as_float(q.y);
        a0 = fmaf(r[f0], nn, a0);
        a1 = fmaf(r[f1], nn, a1);
        a2 = fmaf(r[f2], nn, a2);
    }

    a0 += bias[f0]; a1 += bias[f1]; a2 += bias[f2];
    if (do_prelu) {
        float a = aptr[0];
        a0 = (a0 > 0.f) ? a0 : a * a0;
        a1 = (a1 > 0.f) ? a1 : a * a1;
        a2 = (a2 > 0.f) ? a2 : a * a2;
    }
    float* o = out + (size_t)warp * 96;
    o[f0] = a0; o[f1] = a1; o[f2] = a2;
}

// ---------------- launch ---------------------------------------------------
extern "C" void kernel_launch(void* const* d_in, const int* in_sizes, int n_in,
                              void* d_out, int out_size) {
    const float* x  = (const float*)d_in[0];
    const int*   ei = (const int*)d_in[1];      // int32! (JAX x64 disabled)
    const float* W1 = (const float*)d_in[2];
    const float* b1 = (const float*)d_in[3];
    const float* a1 = (const float*)d_in[4];
    const float* W2 = (const float*)d_in[5];
    const float* b2 = (const float*)d_in[6];
    float*       out = (float*)d_out;

    int N = in_sizes[0] / D;
    int E = in_sizes[1] / 2;

    int nscan = (N + SCAN_B - 1) / SCAN_B;
    int gemm_blocks = (N + TM - 1) / TM;
    int agg_blocks = (N * 32 + 255) / 256;

    // GEMM1 is independent of the CSR build — run it first.
    k_gemm<<<gemm_blocks, 192>>>(x, W1, N, 0);

    // graph preprocessing (shared by both layers); dinv fused into scan1
    k_zero_counts<<<(N + 255) / 256, 256>>>(N);
    k_hist<<<(E + 255) / 256, 256>>>(ei, E);
    k_scan1<<<nscan, SCAN_B>>>(N);
    k_scan2<<<1, 128>>>(nscan, N);
    k_scan3<<<nscan, SCAN_B>>>(N);
    k_scatter<<<(E + 255) / 256, 256>>>(ei, E);

    // layer 1 aggregate + PReLU -> g_h2
    k_agg<<<agg_blocks, 256>>>(b1, a1, out, N, 1, 0);
    // layer 2: g_h2 @ W2 -> g_h1 ; aggregate -> out
    k_gemm<<<gemm_blocks, 192>>>(x /*unused*/, W2, N, 1);
    k_agg<<<agg_blocks, 256>>>(b2, a1, out, N, 0, 1);
}

// round 7
// speedup vs baseline: 1.1438x; 1.0384x over previous
#include <cuda_runtime.h>
#include <cuda_fp16.h>

#define D 96
#define NMAX 50000
#define EMAX 800000
#define SCAN_B 512
#define NSCANBLK ((NMAX + SCAN_B - 1) / SCAN_B)   // 98

typedef unsigned long long ull;

// ---------------- scratch (static device globals; no allocation) ----------
__device__ int    g_counts[NMAX];          // zero at load; re-zeroed by k_scan1
__device__ int    g_rowptr[NMAX + 1];
__device__ int    g_cursor[NMAX];
__device__ float  g_dinv[NMAX];
__device__ int2   g_adj[EMAX];             // {src, bitcast(norm)}
__device__ __half g_hh[(size_t)NMAX * D];  // GEMM output (fp16, gather source)
__device__ float  g_h2[(size_t)NMAX * D];  // agg output / GEMM2 input (fp32)
__device__ int    g_blockSums[NSCANBLK + 2];

// ---------------- packed f32x2 helpers -------------------------------------
__device__ __forceinline__ ull pack2(float lo, float hi) {
    ull r; asm("mov.b64 %0, {%1, %2};" : "=l"(r) : "f"(lo), "f"(hi)); return r;
}
__device__ __forceinline__ void unpack2(ull v, float& lo, float& hi) {
    asm("mov.b64 {%0, %1}, %2;" : "=f"(lo), "=f"(hi) : "l"(v));
}
__device__ __forceinline__ void ffma2(ull& d, ull a, ull b) {
    asm("fma.rn.f32x2 %0, %1, %2, %0;" : "+l"(d) : "l"(a), "l"(b));
}

// ---------------- graph preprocessing -------------------------------------
// edge_index is int32 (JAX x64 disabled downcasts int64 -> int32)
__global__ void k_hist(const int* __restrict__ ei, int E) {
    int e = blockIdx.x * blockDim.x + threadIdx.x;
    if (e < E) {
        int d = ei[E + e];
        atomicAdd(&g_counts[d], 1);
    }
}

// block-local exclusive scan of counts -> g_rowptr, block totals -> g_blockSums.
// fuses dinv compute AND re-zeroes counts for the next launch.
__global__ void k_scan1(int n) {
    __shared__ int wsum[16];
    int i = blockIdx.x * SCAN_B + threadIdx.x;
    int lane = threadIdx.x & 31, wid = threadIdx.x >> 5;
    int v = 0;
    if (i < n) {
        v = g_counts[i];
        g_dinv[i] = rsqrtf((float)(v + 1));   // +1 self loop
        g_counts[i] = 0;                      // restore invariant
    }
    int x = v;
#pragma unroll
    for (int o = 1; o < 32; o <<= 1) {
        int t = __shfl_up_sync(0xFFFFFFFFu, x, o);
        if (lane >= o) x += t;
    }
    if (lane == 31) wsum[wid] = x;
    __syncthreads();
    if (wid == 0) {
        int s = (lane < 16) ? wsum[lane] : 0;
#pragma unroll
        for (int o = 1; o < 16; o <<= 1) {
            int t = __shfl_up_sync(0xFFFFFFFFu, s, o);
            if (lane >= o) s += t;
        }
        if (lane < 16) wsum[lane] = s;
    }
    __syncthreads();
    int base = (wid > 0) ? wsum[wid - 1] : 0;
    if (i < n) g_rowptr[i] = base + x - v;           // exclusive (block-local)
    if (threadIdx.x == SCAN_B - 1) g_blockSums[blockIdx.x] = base + x;
}

// adds cross-block prefix (computed per-block via warp reduce over blockSums)
__global__ void k_scan3(int n, int nb) {
    __shared__ int sbase;
    int bid = blockIdx.x;
    if (threadIdx.x < 32) {
        int lane = threadIdx.x;
        int acc = 0;
        for (int b = lane; b < bid; b += 32) acc += g_blockSums[b];
#pragma unroll
        for (int o = 16; o; o >>= 1) acc += __shfl_xor_sync(0xFFFFFFFFu, acc, o);
        if (lane == 0) sbase = acc;
    }
    __syncthreads();
    int base = sbase;
    int i = bid * SCAN_B + threadIdx.x;
    if (i < n) {
        int v = g_rowptr[i] + base;
        g_rowptr[i] = v;
        g_cursor[i] = v;
    }
    if (bid == nb - 1 && threadIdx.x == 0) {
        int tot = base;
        for (int b = bid; b < nb; b++) tot += g_blockSums[b];
        g_rowptr[n] = tot;                   // total = E
    }
}

__global__ void k_scatter(const int* __restrict__ ei, int E) {
    int e = blockIdx.x * blockDim.x + threadIdx.x;
    if (e < E) {
        int s = ei[e];
        int d = ei[E + e];
        int pos = atomicAdd(&g_cursor[d], 1);
        float norm = g_dinv[s] * g_dinv[d];
        g_adj[pos] = make_int2(s, __float_as_int(norm));
    }
}

// ---------------- dense GEMM: Hh[N,96] = X[N,96] @ W[96,96] (fp16 out) -----
// Register tile per thread: 4 contiguous features x 2 row-pairs (f32x2 packed).
// block: 192 threads, TM=32 nodes. tid -> f0=(tid%24)*4, p0=(tid/24)*2.
// src_sel: 0 = Xext (fp32), 1 = g_h2 (fp32). Output: g_hh (fp16).
#define TM 32
__global__ __launch_bounds__(192) void k_gemm(const float* __restrict__ Xext,
                                              const float* __restrict__ W,
                                              int n, int src_sel) {
    __shared__ __align__(16) float Ws[96 * 96];
    __shared__ __align__(16) ull Xs2[16][96];   // Xs2[p][k] = {X[2p][k], X[2p+1][k]}
    const float* X = src_sel ? (const float*)g_h2 : Xext;
    __half* Y = (__half*)g_hh;

    int tid = threadIdx.x;

    {
        const float4* Wv = (const float4*)W;
        float4* Wsv = (float4*)Ws;
        for (int i = tid; i < 96 * 96 / 4; i += 192) Wsv[i] = Wv[i];
    }

    int n0 = blockIdx.x * TM;
    int rows = min(TM, n - n0);
    float* Xsf = (float*)&Xs2[0][0];
    for (int i = tid; i < TM * 96; i += 192) {
        int m = i / 96, k = i % 96;     // coalesced global read
        float v = (m < rows) ? X[(size_t)(n0 + m) * 96 + k] : 0.f;
        Xsf[((m >> 1) * 96 + k) * 2 + (m & 1)] = v;
    }
    __syncthreads();

    int f0 = (tid % 24) * 4;
    int p0 = (tid / 24) * 2;

    ull acc[4][2];
#pragma unroll
    for (int f = 0; f < 4; f++)
#pragma unroll
        for (int p = 0; p < 2; p++) acc[f][p] = 0ull;

#pragma unroll 6
    for (int k = 0; k < 96; k += 2) {
        float4 w0 = *(const float4*)&Ws[k * 96 + f0];
        float4 w1 = *(const float4*)&Ws[(k + 1) * 96 + f0];
        ulonglong2 x0 = *(const ulonglong2*)&Xs2[p0][k];
        ulonglong2 x1 = *(const ulonglong2*)&Xs2[p0 + 1][k];

        ull pw00 = pack2(w0.x, w0.x), pw01 = pack2(w0.y, w0.y);
        ull pw02 = pack2(w0.z, w0.z), pw03 = pack2(w0.w, w0.w);
        ull pw10 = pack2(w1.x, w1.x), pw11 = pack2(w1.y, w1.y);
        ull pw12 = pack2(w1.z, w1.z), pw13 = pack2(w1.w, w1.w);

        ffma2(acc[0][0], x0.x, pw00); ffma2(acc[1][0], x0.x, pw01);
        ffma2(acc[2][0], x0.x, pw02); ffma2(acc[3][0], x0.x, pw03);
        ffma2(acc[0][0], x0.y, pw10); ffma2(acc[1][0], x0.y, pw11);
        ffma2(acc[2][0], x0.y, pw12); ffma2(acc[3][0], x0.y, pw13);

        ffma2(acc[0][1], x1.x, pw00); ffma2(acc[1][1], x1.x, pw01);
        ffma2(acc[2][1], x1.x, pw02); ffma2(acc[3][1], x1.x, pw03);
        ffma2(acc[0][1], x1.y, pw10); ffma2(acc[1][1], x1.y, pw11);
        ffma2(acc[2][1], x1.y, pw12); ffma2(acc[3][1], x1.y, pw13);
    }

#pragma unroll
    for (int p = 0; p < 2; p++) {
        int m0 = (p0 + p) * 2;
        float4 lo4, hi4;
        unpack2(acc[0][p], lo4.x, hi4.x);
        unpack2(acc[1][p], lo4.y, hi4.y);
        unpack2(acc[2][p], lo4.z, hi4.z);
        unpack2(acc[3][p], lo4.w, hi4.w);
        if (n0 + m0 < n) {
            __half2 a = __floats2half2_rn(lo4.x, lo4.y);
            __half2 b = __floats2half2_rn(lo4.z, lo4.w);
            *(__half2*)&Y[(size_t)(n0 + m0) * 96 + f0]     = a;
            *(__half2*)&Y[(size_t)(n0 + m0) * 96 + f0 + 2] = b;
        }
        if (n0 + m0 + 1 < n) {
            __half2 a = __floats2half2_rn(hi4.x, hi4.y);
            __half2 b = __floats2half2_rn(hi4.z, hi4.w);
            *(__half2*)&Y[(size_t)(n0 + m0 + 1) * 96 + f0]     = a;
            *(__half2*)&Y[(size_t)(n0 + m0 + 1) * 96 + f0 + 2] = b;
        }
    }
}

// ---------------- aggregation: one warp per node ---------------------------
// reads g_hh (fp16); writes g_h2 fp32 (dst_sel=0) or external out (dst_sel=1).
// out[n,f] = b[f] + sum_{incoming e} h[src_e,f]*norm_e + h[n,f]*dinv[n]^2
__global__ __launch_bounds__(256) void k_agg(const float* __restrict__ bias,
                                             const float* __restrict__ aptr,
                                             float* __restrict__ outExt,
                                             int n, int do_prelu, int dst_sel) {
    int warp = (blockIdx.x * blockDim.x + threadIdx.x) >> 5;
    int lane = threadIdx.x & 31;
    if (warp >= n) return;

    const __half* h = (const __half*)g_hh;
    float* out = (dst_sel == 0) ? (float*)g_h2 : outExt;

    int f0 = lane, f1 = lane + 32, f2 = lane + 64;
    float dn = g_dinv[warp];
    float dn2 = dn * dn;
    const __half* hr = h + (size_t)warp * 96;
    float a0 = __half2float(hr[f0]) * dn2;
    float a1 = __half2float(hr[f1]) * dn2;
    float a2 = __half2float(hr[f2]) * dn2;

    int e = g_rowptr[warp];
    int end = g_rowptr[warp + 1];

    for (; e + 1 < end; e += 2) {
        int2 q0 = g_adj[e];
        int2 q1 = g_adj[e + 1];
        const __half* r0 = h + (size_t)q0.x * 96;
        const __half* r1 = h + (size_t)q1.x * 96;
        float n0 = __int_as_float(q0.y);
        float n1 = __int_as_float(q1.y);
        float v00 = __half2float(r0[f0]), v01 = __half2float(r0[f1]), v02 = __half2float(r0[f2]);
        float v10 = __half2float(r1[f0]), v11 = __half2float(r1[f1]), v12 = __half2float(r1[f2]);
        a0 = fmaf(v00, n0, a0); a1 = fmaf(v01, n0, a1); a2 = fmaf(v02, n0, a2);
        a0 = fmaf(v10, n1, a0); a1 = fmaf(v11, n1, a1); a2 = fmaf(v12, n1, a2);
    }
    if (e < end) {
        int2 q = g_adj[e];
        const __half* r = h + (size_t)q.x * 96;
        float nn = __int_as_float(q.y);
        a0 = fmaf(__half2float(r[f0]), nn, a0);
        a1 = fmaf(__half2float(r[f1]), nn, a1);
        a2 = fmaf(__half2float(r[f2]), nn, a2);
    }

    a0 += bias[f0]; a1 += bias[f1]; a2 += bias[f2];
    if (do_prelu) {
        float a = aptr[0];
        a0 = (a0 > 0.f) ? a0 : a * a0;
        a1 = (a1 > 0.f) ? a1 : a * a1;
        a2 = (a2 > 0.f) ? a2 : a * a2;
    }
    float* o = out + (size_t)warp * 96;
    o[f0] = a0; o[f1] = a1; o[f2] = a2;
}

// ---------------- launch ---------------------------------------------------
extern "C" void kernel_launch(void* const* d_in, const int* in_sizes, int n_in,
                              void* d_out, int out_size) {
    const float* x  = (const float*)d_in[0];
    const int*   ei = (const int*)d_in[1];      // int32! (JAX x64 disabled)
    const float* W1 = (const float*)d_in[2];
    const float* b1 = (const float*)d_in[3];
    const float* a1 = (const float*)d_in[4];
    const float* W2 = (const float*)d_in[5];
    const float* b2 = (const float*)d_in[6];
    float*       out = (float*)d_out;

    int N = in_sizes[0] / D;
    int E = in_sizes[1] / 2;

    int nscan = (N + SCAN_B - 1) / SCAN_B;
    int gemm_blocks = (N + TM - 1) / TM;
    int agg_blocks = (N * 32 + 255) / 256;

    // GEMM1 is independent of the CSR build — run it first.
    k_gemm<<<gemm_blocks, 192>>>(x, W1, N, 0);

    // graph preprocessing; counts zeroing + dinv fused into scan1,
    // cross-block prefix fused into scan3.
    k_hist<<<(E + 255) / 256, 256>>>(ei, E);
    k_scan1<<<nscan, SCAN_B>>>(N);
    k_scan3<<<nscan, SCAN_B>>>(N, nscan);
    k_scatter<<<(E + 255) / 256, 256>>>(ei, E);

    // layer 1 aggregate + PReLU -> g_h2
    k_agg<<<agg_blocks, 256>>>(b1, a1, out, N, 1, 0);
    // layer 2: g_h2 @ W2 -> g_hh ; aggregate -> out
    k_gemm<<<gemm_blocks, 192>>>(x /*unused*/, W2, N, 1);
    k_agg<<<agg_blocks, 256>>>(b2, a1, out, N, 0, 1);
}